// round 16
// baseline (speedup 1.0000x reference)
#include <cuda_runtime.h>
#include <cstdint>

// GrCNetSpmm: out[r, f] += edge_w[e, f] for r = edge[0][e].
// Two-level binning pipeline (2 launches):
//  A: bin edges by row>>6 (64 rows/bin). Per-block SMEM histogram, ONE global
//     atomicAdd per (block,bin) segment reservation (kills the 16-way per-row
//     atomic contention of the old build), SMEM cursors for positions, store
//     packed (localrow<<20 | edge) into the bin's segment.
//  B: one block per bin: load packed words (coalesced, L2-hot), build a 64-row
//     CSR in SMEM (hist+scan+scatter), then per-row register gather with
//     8 independent 256B edge_w reads in flight; coalesced out store; reset
//     g_bincnt[bin]=0 (restores the all-zero invariant for graph replays).

#define MAXNB 1024                    // max bins (N <= 65535, 64 rows/bin)
#define CAP   2048                    // slots per bin (mean ~1024 at E/N=16)
#define CH    8192                    // edges per phase-A block

__device__ int g_bincnt[MAXNB];       // zero-init by CUDA; reset by phase B
__device__ int g_bins[MAXNB * CAP];   // packed (lr<<20 | e)
__device__ int g_is64_fb;             // fallback dtype flag

__device__ __forceinline__ int load_row(const void* rows, int e, int is64) {
    return is64 ? (int)__ldg((const long long*)rows + e)
                : __ldg((const int*)rows + e);
}

// ---- phase A: bin the edges ------------------------------------------------
__global__ void __launch_bounds__(256)
binA_kernel(const void* __restrict__ rows, int E, int N, int NB) {
    __shared__ int s_is64;
    __shared__ int hist[MAXNB];
    __shared__ int gbase[MAXNB];
    __shared__ int cur[MAXNB];
    __shared__ unsigned short srow[CH];

    int tid = threadIdx.x;
    // dtype detect: odd int32 words of int64 data are all zero (< 2^31);
    // random int32 rows are not.
    if (tid < 32) {
        int v = ((const int*)rows)[2 * tid + 1];
        unsigned m = __ballot_sync(0xFFFFFFFFu, v != 0);
        if (tid == 0) s_is64 = (m == 0) ? 1 : 0;
    }
    for (int b = tid; b < NB; b += 256) hist[b] = 0;
    __syncthreads();
    const int is64 = s_is64;

    const int c0 = blockIdx.x * CH;

    // pass 1: histogram bins; cache rows in SMEM (uint16; >=N means invalid)
    for (int i = tid; i < CH; i += 256) {
        int e = c0 + i;
        unsigned short rv = 0xFFFFu;
        if (e < E) {
            int r = load_row(rows, e, is64);
            if ((unsigned)r < (unsigned)N) {
                rv = (unsigned short)r;
                atomicAdd(&hist[r >> 6], 1);
            }
        }
        srow[i] = rv;
    }
    __syncthreads();

    // reserve a global segment per touched bin; init cursors
    for (int b = tid; b < NB; b += 256) {
        int h = hist[b];
        gbase[b] = h ? atomicAdd(&g_bincnt[b], h) : 0;
        cur[b] = 0;
    }
    __syncthreads();

    // pass 2: place packed words at gbase[bin] + local position
    for (int i = tid; i < CH; i += 256) {
        int r = srow[i];
        if (r < N) {
            int bin = r >> 6;
            int p = atomicAdd(&cur[bin], 1);      // SMEM atomic (cheap)
            int dst = gbase[bin] + p;
            if (dst < CAP)
                g_bins[bin * CAP + dst] = ((r & 63) << 20) | (c0 + i);
        }
    }
}

// ---- phase B: per-bin CSR in SMEM + register gather -------------------------
__global__ void __launch_bounds__(256)
binB_kernel(const float2* __restrict__ w, float2* __restrict__ out, int N) {
    __shared__ int h[64];
    __shared__ int offs[65];
    __shared__ int cur[64];
    __shared__ int tmp[64];
    __shared__ int csr[CAP];

    int tid = threadIdx.x;
    int bin = blockIdx.x;
    int cnt = g_bincnt[bin];
    if (cnt > CAP) cnt = CAP;

    if (tid < 64) h[tid] = 0;
    __syncthreads();

    const int* seg = g_bins + bin * CAP;

    // hist of local rows
    for (int i = tid; i < cnt; i += 256)
        atomicAdd(&h[__ldg(seg + i) >> 20], 1);
    __syncthreads();

    // exclusive scan of h[0..63] -> offs
    if (tid < 64) tmp[tid] = h[tid];
    __syncthreads();
    for (int d = 1; d < 64; d <<= 1) {
        int v = 0;
        if (tid < 64 && tid >= d) v = tmp[tid - d];
        __syncthreads();
        if (tid < 64) tmp[tid] += v;
        __syncthreads();
    }
    if (tid < 64) { offs[tid + 1] = tmp[tid]; cur[tid] = (tid == 0) ? 0 : tmp[tid - 1]; }
    if (tid == 0) offs[0] = 0;
    __syncthreads();

    // scatter edge ids into SMEM CSR
    for (int i = tid; i < cnt; i += 256) {
        int wv = __ldg(seg + i);
        int lr = wv >> 20;
        int p = atomicAdd(&cur[lr], 1);
        csr[p] = wv & 0xFFFFF;
    }
    __syncthreads();

    // gather: 8 warps x 8 local rows; lane = float2 chunk (256B per edge)
    int wid = tid >> 5;
    int lane = tid & 31;
    for (int lr = wid; lr < 64; lr += 8) {
        int row = (bin << 6) + lr;
        if (row >= N) break;
        int s = offs[lr], t = offs[lr + 1];
        int m = t - s;

        float2 acc = make_float2(0.f, 0.f);
        int k = 0;
        for (; k + 8 <= m; k += 8) {              // 8 independent 256B reads
            int a0 = csr[s + k + 0], a1 = csr[s + k + 1];
            int a2 = csr[s + k + 2], a3 = csr[s + k + 3];
            int a4 = csr[s + k + 4], a5 = csr[s + k + 5];
            int a6 = csr[s + k + 6], a7 = csr[s + k + 7];
            float2 v0 = __ldg(w + (size_t)a0 * 32 + lane);
            float2 v1 = __ldg(w + (size_t)a1 * 32 + lane);
            float2 v2 = __ldg(w + (size_t)a2 * 32 + lane);
            float2 v3 = __ldg(w + (size_t)a3 * 32 + lane);
            float2 v4 = __ldg(w + (size_t)a4 * 32 + lane);
            float2 v5 = __ldg(w + (size_t)a5 * 32 + lane);
            float2 v6 = __ldg(w + (size_t)a6 * 32 + lane);
            float2 v7 = __ldg(w + (size_t)a7 * 32 + lane);
            acc.x += ((v0.x + v1.x) + (v2.x + v3.x))
                   + ((v4.x + v5.x) + (v6.x + v7.x));
            acc.y += ((v0.y + v1.y) + (v2.y + v3.y))
                   + ((v4.y + v5.y) + (v6.y + v7.y));
        }
        for (; k + 2 <= m; k += 2) {
            int a0 = csr[s + k + 0], a1 = csr[s + k + 1];
            float2 v0 = __ldg(w + (size_t)a0 * 32 + lane);
            float2 v1 = __ldg(w + (size_t)a1 * 32 + lane);
            acc.x += v0.x + v1.x;
            acc.y += v0.y + v1.y;
        }
        if (k < m) {
            int a0 = csr[s + k];
            float2 v = __ldg(w + (size_t)a0 * 32 + lane);
            acc.x += v.x; acc.y += v.y;
        }
        out[(size_t)row * 32 + lane] = acc;
    }

    __syncthreads();
    if (tid == 0) g_bincnt[bin] = 0;              // restore zero invariant
}

// ---- fallback (generic shapes): detect + zero + RED scatter ----------------
__global__ void detect_fb_kernel(const int* __restrict__ w32) {
    int v = w32[2 * threadIdx.x + 1];
    unsigned m = __ballot_sync(0xFFFFFFFFu, v != 0);
    if (threadIdx.x == 0) g_is64_fb = (m == 0) ? 1 : 0;
}
__global__ void zero_out_kernel(float4* __restrict__ out, int n4) {
    int i = blockIdx.x * blockDim.x + threadIdx.x;
    if (i < n4) out[i] = make_float4(0.f, 0.f, 0.f, 0.f);
}
__global__ void segsum_red_kernel(const void* __restrict__ rows_raw,
                                  const float4* __restrict__ w,
                                  float* __restrict__ out,
                                  int total, int F4, int F, int N) {
    int i = blockIdx.x * blockDim.x + threadIdx.x;
    if (i >= total) return;
    int e = i / F4, j = i % F4;
    int r = load_row(rows_raw, e, g_is64_fb);
    float4 v = __ldg(w + i);
    if ((unsigned)r < (unsigned)N) {
        float* dst = out + (size_t)r * F + (size_t)j * 4;
        asm volatile("red.global.add.v4.f32 [%0], {%1, %2, %3, %4};"
                     :: "l"(dst), "f"(v.x), "f"(v.y), "f"(v.z), "f"(v.w)
                     : "memory");
    }
}

extern "C" void kernel_launch(void* const* d_in, const int* in_sizes, int n_in,
                              void* d_out, int out_size) {
    const void* edge = d_in[0];                    // [2, E]; edge[0] = rows
    const float* edge_w = (const float*)d_in[1];   // [E, F] f32

    int E = in_sizes[0] / 2;
    int F = in_sizes[1] / E;                       // 64
    int N = out_size / F;                          // 50000
    int NB = (N + 63) >> 6;

    // pack needs e < 2^20 and uint16 rows; CAP needs modest avg degree
    if (F == 64 && N <= 65535 && E < (1 << 20) && NB <= MAXNB && E <= 20 * N) {
        int blocksA = (E + CH - 1) / CH;
        binA_kernel<<<blocksA, 256>>>(edge, E, N, NB);
        binB_kernel<<<NB, 256>>>((const float2*)edge_w, (float2*)d_out, N);
    } else {
        int F4 = F / 4;
        int total = E * F4;
        int n4 = out_size / 4;
        int threads = 256;
        detect_fb_kernel<<<1, 32>>>((const int*)edge);
        zero_out_kernel<<<(n4 + threads - 1) / threads, threads>>>(
            (float4*)d_out, n4);
        segsum_red_kernel<<<(total + threads - 1) / threads, threads>>>(
            edge, (const float4*)edge_w, (float*)d_out, total, F4, F, N);
    }
}

// round 17
// speedup vs baseline: 1.2040x; 1.2040x over previous
#include <cuda_runtime.h>
#include <cstdint>

// GrCNetSpmm: out[r, f] += edge_w[e, f] for r = edge[0][e].
// Two-level binning, NO global atomics, NO carried global state:
//  A: one block per 4096-edge chunk. Positions via SMEM atomics only; edge
//     packed as ((r&63)<<20 | e) into fixed cell g_cell[bin][chunk][32];
//     per-(bin,chunk) counts written to g_cellcnt (fully overwritten -> no
//     reset needed for graph replays).
//  B: one block per 64-row bin. Stage the bin's entries (contiguous cells)
//     into SMEM via scan + binary-search copy, build a 64-row CSR in SMEM,
//     then per-row register gather with 8 independent 256B reads in flight.

#define CH      4096                  // edges per phase-A chunk
#define CELLCAP 32                    // entries per (bin,chunk) cell (128B)
#define MAXNB   1024                  // bins (64 rows each) -> N <= 65536
#define MAXNC   256                   // chunks -> E <= 2^20
#define BCAP    2048                  // max entries per bin

__device__ int g_cellcnt[MAXNB * MAXNC];           // overwritten every call
__device__ int g_cell[MAXNB * MAXNC * CELLCAP];    // packed (lr<<20 | e)
__device__ int g_is64_fb;                          // fallback dtype flag

__device__ __forceinline__ int load_row(const void* rows, int e, int is64) {
    return is64 ? (int)__ldg((const long long*)rows + e)
                : __ldg((const int*)rows + e);
}

// ---- phase A: chunk -> cells, SMEM positions only ---------------------------
__global__ void __launch_bounds__(512)
binA_kernel(const void* __restrict__ rows, int E, int N, int NB, int NC) {
    __shared__ int s_is64;
    __shared__ int cur[MAXNB];
    int tid = threadIdx.x;

    // dtype detect: odd int32 words of int64 data are all zero (< 2^31);
    // random int32 rows are not.
    if (tid < 32) {
        int v = ((const int*)rows)[2 * tid + 1];
        unsigned m = __ballot_sync(0xFFFFFFFFu, v != 0);
        if (tid == 0) s_is64 = (m == 0) ? 1 : 0;
    }
    for (int b = tid; b < NB; b += 512) cur[b] = 0;
    __syncthreads();
    const int is64 = s_is64;
    const int chunk = blockIdx.x;
    const int base = chunk * CH;

    // front-batch the 8 index loads, then smem-atomic + store per edge
    int r[8];
    #pragma unroll
    for (int u = 0; u < 8; u++) {
        int e = base + tid + u * 512;
        r[u] = (e < E) ? load_row(rows, e, is64) : -1;
    }
    #pragma unroll
    for (int u = 0; u < 8; u++) {
        if ((unsigned)r[u] < (unsigned)N) {
            int e = base + tid + u * 512;
            int bin = r[u] >> 6;
            int p = atomicAdd(&cur[bin], 1);
            if (p < CELLCAP)
                g_cell[(bin * NC + chunk) * CELLCAP + p] =
                    ((r[u] & 63) << 20) | e;
        }
    }
    __syncthreads();
    for (int b = tid; b < NB; b += 512)
        g_cellcnt[b * NC + chunk] = cur[b];
}

// ---- phase B: per-bin CSR in SMEM + register gather -------------------------
__global__ void __launch_bounds__(256)
binB_kernel(const float2* __restrict__ w, float2* __restrict__ out,
            int N, int NC) {
    __shared__ int pc[MAXNC];          // cell counts -> inclusive prefix
    __shared__ int ent[BCAP];          // staged packed entries
    __shared__ int csr[BCAP];          // edge ids ordered by local row
    __shared__ int h[64], tmp[64], offs[65], cur[64];

    int tid = threadIdx.x;
    int bin = blockIdx.x;

    // 1. load cell counts (contiguous, coalesced), clamp
    for (int c = tid; c < MAXNC; c += 256) {
        int v = 0;
        if (c < NC) v = min(g_cellcnt[bin * NC + c], CELLCAP);
        pc[c] = v;
    }
    __syncthreads();

    // 2. inclusive scan over 256 slots (Hillis-Steele)
    for (int d = 1; d < 256; d <<= 1) {
        int v = (tid >= d) ? pc[tid - d] : 0;
        __syncthreads();
        pc[tid] += v;
        __syncthreads();
    }
    int total = pc[MAXNC - 1];
    if (total > BCAP) total = BCAP;

    // 3. stage entries: binary-search the owning cell per entry index
    for (int i = tid; i < total; i += 256) {
        int lo = 0, hi = NC - 1;       // smallest c with pc[c] > i
        while (lo < hi) {
            int mid = (lo + hi) >> 1;
            if (pc[mid] > i) hi = mid; else lo = mid + 1;
        }
        int off = i - (lo ? pc[lo - 1] : 0);
        ent[i] = g_cell[(bin * NC + lo) * CELLCAP + off];
    }
    if (tid < 64) h[tid] = 0;
    __syncthreads();

    // 4. hist by local row
    for (int i = tid; i < total; i += 256)
        atomicAdd(&h[ent[i] >> 20], 1);
    __syncthreads();

    // 5. scan h -> offs, cur
    if (tid < 64) tmp[tid] = h[tid];
    __syncthreads();
    for (int d = 1; d < 64; d <<= 1) {
        int v = 0;
        if (tid < 64 && tid >= d) v = tmp[tid - d];
        __syncthreads();
        if (tid < 64) tmp[tid] += v;
        __syncthreads();
    }
    if (tid < 64) { offs[tid + 1] = tmp[tid]; cur[tid] = (tid == 0) ? 0 : tmp[tid - 1]; }
    if (tid == 0) offs[0] = 0;
    __syncthreads();

    // 6. scatter edge ids into CSR order
    for (int i = tid; i < total; i += 256) {
        int v = ent[i];
        int p = atomicAdd(&cur[v >> 20], 1);
        csr[p] = v & 0xFFFFF;
    }
    __syncthreads();

    // 7. gather: 8 warps x 8 local rows; lane = float2 chunk (256B per edge)
    int wid = tid >> 5;
    int lane = tid & 31;
    for (int lr = wid; lr < 64; lr += 8) {
        int row = (bin << 6) + lr;
        if (row >= N) break;
        int s = offs[lr], t = offs[lr + 1];
        int m = t - s;

        float2 acc = make_float2(0.f, 0.f);
        int k = 0;
        for (; k + 8 <= m; k += 8) {              // 8 independent 256B reads
            int a0 = csr[s + k + 0], a1 = csr[s + k + 1];
            int a2 = csr[s + k + 2], a3 = csr[s + k + 3];
            int a4 = csr[s + k + 4], a5 = csr[s + k + 5];
            int a6 = csr[s + k + 6], a7 = csr[s + k + 7];
            float2 v0 = __ldg(w + (size_t)a0 * 32 + lane);
            float2 v1 = __ldg(w + (size_t)a1 * 32 + lane);
            float2 v2 = __ldg(w + (size_t)a2 * 32 + lane);
            float2 v3 = __ldg(w + (size_t)a3 * 32 + lane);
            float2 v4 = __ldg(w + (size_t)a4 * 32 + lane);
            float2 v5 = __ldg(w + (size_t)a5 * 32 + lane);
            float2 v6 = __ldg(w + (size_t)a6 * 32 + lane);
            float2 v7 = __ldg(w + (size_t)a7 * 32 + lane);
            acc.x += ((v0.x + v1.x) + (v2.x + v3.x))
                   + ((v4.x + v5.x) + (v6.x + v7.x));
            acc.y += ((v0.y + v1.y) + (v2.y + v3.y))
                   + ((v4.y + v5.y) + (v6.y + v7.y));
        }
        for (; k + 2 <= m; k += 2) {
            int a0 = csr[s + k + 0], a1 = csr[s + k + 1];
            float2 v0 = __ldg(w + (size_t)a0 * 32 + lane);
            float2 v1 = __ldg(w + (size_t)a1 * 32 + lane);
            acc.x += v0.x + v1.x;
            acc.y += v0.y + v1.y;
        }
        if (k < m) {
            int a0 = csr[s + k];
            float2 v = __ldg(w + (size_t)a0 * 32 + lane);
            acc.x += v.x; acc.y += v.y;
        }
        out[(size_t)row * 32 + lane] = acc;
    }
}

// ---- fallback (generic shapes): detect + zero + RED scatter ----------------
__global__ void detect_fb_kernel(const int* __restrict__ w32) {
    int v = w32[2 * threadIdx.x + 1];
    unsigned m = __ballot_sync(0xFFFFFFFFu, v != 0);
    if (threadIdx.x == 0) g_is64_fb = (m == 0) ? 1 : 0;
}
__global__ void zero_out_kernel(float4* __restrict__ out, int n4) {
    int i = blockIdx.x * blockDim.x + threadIdx.x;
    if (i < n4) out[i] = make_float4(0.f, 0.f, 0.f, 0.f);
}
__global__ void segsum_red_kernel(const void* __restrict__ rows_raw,
                                  const float4* __restrict__ w,
                                  float* __restrict__ out,
                                  int total, int F4, int F, int N) {
    int i = blockIdx.x * blockDim.x + threadIdx.x;
    if (i >= total) return;
    int e = i / F4, j = i % F4;
    int r = load_row(rows_raw, e, g_is64_fb);
    float4 v = __ldg(w + i);
    if ((unsigned)r < (unsigned)N) {
        float* dst = out + (size_t)r * F + (size_t)j * 4;
        asm volatile("red.global.add.v4.f32 [%0], {%1, %2, %3, %4};"
                     :: "l"(dst), "f"(v.x), "f"(v.y), "f"(v.z), "f"(v.w)
                     : "memory");
    }
}

extern "C" void kernel_launch(void* const* d_in, const int* in_sizes, int n_in,
                              void* d_out, int out_size) {
    const void* edge = d_in[0];                    // [2, E]; edge[0] = rows
    const float* edge_w = (const float*)d_in[1];   // [E, F] f32

    int E = in_sizes[0] / 2;
    int F = in_sizes[1] / E;                       // 64
    int N = out_size / F;                          // 50000
    int NB = (N + 63) >> 6;
    int NC = (E + CH - 1) / CH;

    // guards: packing needs e < 2^20; cell/bin capacities need N large and
    // modest average degree (uniform-ish rows).
    if (F == 64 && N >= 32768 && N <= 65536 && E <= (1 << 20) &&
        NC <= MAXNC && E <= 20 * N) {
        binA_kernel<<<NC, 512>>>(edge, E, N, NB, NC);
        binB_kernel<<<NB, 256>>>((const float2*)edge_w, (float2*)d_out, N, NC);
    } else {
        int F4 = F / 4;
        int total = E * F4;
        int n4 = out_size / 4;
        int threads = 256;
        detect_fb_kernel<<<1, 32>>>((const int*)edge);
        zero_out_kernel<<<(n4 + threads - 1) / threads, threads>>>(
            (float4*)d_out, n4);
        segsum_red_kernel<<<(total + threads - 1) / threads, threads>>>(
            edge, (const float4*)edge_w, (float*)d_out, total, F4, F, N);
    }
}